// round 1
// baseline (speedup 1.0000x reference)
#include <cuda_runtime.h>

// Problem constants
#define BB   64
#define CC   256
#define NTOK 1600      // T*V = 64*25
#define VQ   25
#define HH   8
#define HD   32

// Scratch (device globals — allocation-free rule)
__device__ float g_K[BB * CC * NTOK];   // [b][co][n]  ~105 MB
__device__ float g_V[BB * CC * NTOK];   // [b][co][n]  ~105 MB
__device__ float g_Q[BB * VQ * CC];     // [b][v][co]  (pre-scaled by temp/sqrt(hd))
__device__ float g_O[BB * VQ * CC];     // [b][v][co]  attention output

// ---------------- packed fp32 helpers (FFMA2 path) ----------------
__device__ __forceinline__ unsigned long long pk2(float x, float y) {
    unsigned long long r;
    asm("mov.b64 %0, {%1, %2};" : "=l"(r) : "f"(x), "f"(y));
    return r;
}
__device__ __forceinline__ void unpk(unsigned long long v, float& x, float& y) {
    asm("mov.b64 {%0, %1}, %2;" : "=f"(x), "=f"(y) : "l"(v));
}
__device__ __forceinline__ void ffma2(unsigned long long& d, unsigned long long a, unsigned long long b) {
    asm("fma.rn.f32x2 %0, %1, %2, %0;" : "+l"(d) : "l"(a), "l"(b));
}

// ---------------------------------------------------------------
// Q projection: g_Q[b][v][co] = (sum_c q_w[co][c] * x_cls[b][c][v]) * temp[h]*scale
// ---------------------------------------------------------------
__global__ __launch_bounds__(256)
void qproj_kernel(const float* __restrict__ x_cls,
                  const float* __restrict__ q_w,
                  const float* __restrict__ temp) {
    const int b = blockIdx.x;
    __shared__ float xs[CC * VQ];
    const int tid = threadIdx.x;            // tid == co
    for (int i = tid; i < CC * VQ; i += 256) xs[i] = x_cls[b * CC * VQ + i];
    __syncthreads();

    float acc[VQ];
#pragma unroll
    for (int v = 0; v < VQ; v++) acc[v] = 0.f;
    const float* wrow = q_w + tid * CC;
    for (int c = 0; c < CC; c++) {
        float w = wrow[c];
#pragma unroll
        for (int v = 0; v < VQ; v++) acc[v] += w * xs[c * VQ + v];
    }
    const float sc = temp[tid >> 5] * 0.17677669529663687f;  // 1/sqrt(32)
#pragma unroll
    for (int v = 0; v < VQ; v++)
        g_Q[b * (VQ * CC) + v * CC + tid] = acc[v] * sc;
}

// ---------------------------------------------------------------
// Projection GEMM: Out[b][co][n] = sum_c W[co][c] * X[b][c][n]
// Block tile 128(co) x 64(n), K-step 16. 128 threads, microtile 8x8.
// Accumulators are f32x2 pairs along co -> A-frag loads as u64 pairs,
// only the 8 X values per kk need duplication packs.
// ---------------------------------------------------------------
__global__ __launch_bounds__(128, 4)
void proj_gemm_kernel(const float* __restrict__ X,
                      const float* __restrict__ W,
                      int which) {     // 0 -> g_K, 1 -> g_V
    float* __restrict__ Out = which ? g_V : g_K;
    const int b   = blockIdx.z;
    const int co0 = blockIdx.y * 128;
    const int n0  = blockIdx.x * 64;

    __shared__ __align__(16) float Xs[16][64];
    __shared__ __align__(16) float Wt[16][128];

    const int tid = threadIdx.x;
    const int tx = tid & 7;        // n-frag group (x4 + x4 at +32)
    const int ty = tid >> 3;       // co-frag group (8 rows)

    const float* Xb = X + b * (CC * NTOK) + n0;

    unsigned long long acc[32];    // [cp(4 co-pairs)][j(8)]
#pragma unroll
    for (int i = 0; i < 32; i++) acc[i] = 0ull;

    const int lr = tid >> 3;            // X loader row (0..15)
    const int lc = (tid & 7) * 4;       // X loader col group

    for (int k0 = 0; k0 < CC; k0 += 16) {
        // load X tile 16x64 (coalesced float4, two halves)
        float4 xa  = *(const float4*)(Xb + (k0 + lr) * NTOK + lc);
        float4 xb4 = *(const float4*)(Xb + (k0 + lr) * NTOK + lc + 32);
        *(float4*)&Xs[lr][lc]      = xa;
        *(float4*)&Xs[lr][lc + 32] = xb4;
        // load W tile transposed: Wt[kk][co]
        const float* wrow = W + (co0 + tid) * CC + k0;
#pragma unroll
        for (int g = 0; g < 4; g++) {
            float4 w4 = *(const float4*)(wrow + g * 4);
            Wt[g * 4 + 0][tid] = w4.x;
            Wt[g * 4 + 1][tid] = w4.y;
            Wt[g * 4 + 2][tid] = w4.z;
            Wt[g * 4 + 3][tid] = w4.w;
        }
        __syncthreads();

#pragma unroll
        for (int kk = 0; kk < 16; kk++) {
            float4 x0 = *(const float4*)&Xs[kk][tx * 4];
            float4 x1 = *(const float4*)&Xs[kk][tx * 4 + 32];
            unsigned long long px[8];
            px[0] = pk2(x0.x, x0.x); px[1] = pk2(x0.y, x0.y);
            px[2] = pk2(x0.z, x0.z); px[3] = pk2(x0.w, x0.w);
            px[4] = pk2(x1.x, x1.x); px[5] = pk2(x1.y, x1.y);
            px[6] = pk2(x1.z, x1.z); px[7] = pk2(x1.w, x1.w);
            const ulonglong2* wp = (const ulonglong2*)&Wt[kk][ty * 8];
            ulonglong2 a01 = wp[0];
            ulonglong2 a23 = wp[1];
            unsigned long long av[4] = {a01.x, a01.y, a23.x, a23.y};
#pragma unroll
            for (int cp = 0; cp < 4; cp++) {
#pragma unroll
                for (int j = 0; j < 8; j++)
                    ffma2(acc[cp * 8 + j], av[cp], px[j]);
            }
        }
        __syncthreads();
    }

    // epilogue: unpack pairs (co even/odd) and store float4s
    float* Ob = Out + b * (CC * NTOK) + n0;
#pragma unroll
    for (int cp = 0; cp < 4; cp++) {
        float r0[8], r1[8];
#pragma unroll
        for (int j = 0; j < 8; j++) unpk(acc[cp * 8 + j], r0[j], r1[j]);
        const int row = co0 + ty * 8 + cp * 2;
        *(float4*)(Ob + row * NTOK + tx * 4)            = make_float4(r0[0], r0[1], r0[2], r0[3]);
        *(float4*)(Ob + row * NTOK + tx * 4 + 32)       = make_float4(r0[4], r0[5], r0[6], r0[7]);
        *(float4*)(Ob + (row + 1) * NTOK + tx * 4)      = make_float4(r1[0], r1[1], r1[2], r1[3]);
        *(float4*)(Ob + (row + 1) * NTOK + tx * 4 + 32) = make_float4(r1[4], r1[5], r1[6], r1[7]);
    }
}

// ---------------------------------------------------------------
// Attention: one block per (b, head). Flash-style streaming over
// 25 KV tiles of 64 keys. 256 threads.
// ---------------------------------------------------------------
__global__ __launch_bounds__(256)
void attn_kernel() {
    const int b  = blockIdx.x >> 3;
    const int hh = blockIdx.x & 7;

    __shared__ __align__(16) float qs[VQ][33];    // padded vs bank conflicts
    __shared__ __align__(16) float ks[HD][64];    // [d][j]
    __shared__ __align__(16) float vs[64][36];    // transposed [j][d], padded
    __shared__ __align__(16) float ss[VQ][68];    // scores/probs, padded
    __shared__ __align__(16) float outs[VQ][36];  // fp32 accumulators
    __shared__ float mrow[VQ], lrow[VQ], crow[VQ];

    const int tid  = threadIdx.x;
    const int wid  = tid >> 5;
    const int lane = tid & 31;

    for (int i = tid; i < VQ * HD; i += 256) {
        int q = i >> 5, d = i & 31;
        qs[q][d] = g_Q[b * (VQ * CC) + q * CC + hh * HD + d];
    }
    for (int i = tid; i < VQ * 36; i += 256) ((float*)outs)[i] = 0.f;
    if (tid < VQ) { mrow[tid] = -1e30f; lrow[tid] = 0.f; }
    __syncthreads();

    const float* Kb = g_K + b * (CC * NTOK) + hh * HD * NTOK;
    const float* Vb = g_V + b * (CC * NTOK) + hh * HD * NTOK;

    for (int n0 = 0; n0 < NTOK; n0 += 64) {
        // load K tile [d][j] and V tile transposed [j][d]
        for (int i = tid; i < HD * 64; i += 256) {
            int d = i >> 6, j = i & 63;
            float kvv = Kb[d * NTOK + n0 + j];
            float vvv = Vb[d * NTOK + n0 + j];
            ks[d][j] = kvv;
            vs[j][d] = vvv;
        }
        __syncthreads();

        // scores: 25 x 64, vectorized 4-wide along keys
        for (int p = tid; p < VQ * 16; p += 256) {
            int q = p >> 4, jg = (p & 15) * 4;
            float4 s = make_float4(0.f, 0.f, 0.f, 0.f);
#pragma unroll
            for (int d = 0; d < HD; d++) {
                float qv  = qs[q][d];
                float4 k4 = *(const float4*)&ks[d][jg];
                s.x += qv * k4.x; s.y += qv * k4.y;
                s.z += qv * k4.z; s.w += qv * k4.w;
            }
            *(float4*)&ss[q][jg] = s;
        }
        __syncthreads();

        // online softmax update: warp per row
        for (int q = wid; q < VQ; q += 8) {
            float s0 = ss[q][lane], s1 = ss[q][lane + 32];
            float mx = fmaxf(s0, s1);
#pragma unroll
            for (int o = 16; o; o >>= 1) mx = fmaxf(mx, __shfl_xor_sync(0xffffffffu, mx, o));
            float mold = mrow[q];
            float mnew = fmaxf(mold, mx);
            float p0 = __expf(s0 - mnew);
            float p1 = __expf(s1 - mnew);
            ss[q][lane] = p0;
            ss[q][lane + 32] = p1;
            float sum = p0 + p1;
#pragma unroll
            for (int o = 16; o; o >>= 1) sum += __shfl_xor_sync(0xffffffffu, sum, o);
            if (lane == 0) {
                float corr = __expf(mold - mnew);
                crow[q] = corr;
                lrow[q] = lrow[q] * corr + sum;
                mrow[q] = mnew;
            }
        }
        __syncthreads();

        // P @ V : thread handles (q, 4 consecutive d)
        if (tid < VQ * 8) {
            int q = tid >> 3, dg = (tid & 7) * 4;
            float4 o4 = *(float4*)&outs[q][dg];
            float corr = crow[q];
            float4 acc = make_float4(0.f, 0.f, 0.f, 0.f);
#pragma unroll 4
            for (int j = 0; j < 64; j++) {
                float p   = ss[q][j];
                float4 v4 = *(const float4*)&vs[j][dg];
                acc.x += p * v4.x; acc.y += p * v4.y;
                acc.z += p * v4.z; acc.w += p * v4.w;
            }
            o4.x = o4.x * corr + acc.x;
            o4.y = o4.y * corr + acc.y;
            o4.z = o4.z * corr + acc.z;
            o4.w = o4.w * corr + acc.w;
            *(float4*)&outs[q][dg] = o4;
        }
        __syncthreads();
    }

    if (tid < VQ * 8) {
        int q = tid >> 3, dg = (tid & 7) * 4;
        float inv = 1.f / lrow[q];
        float4 o4 = *(float4*)&outs[q][dg];
        *(float4*)(g_O + b * (VQ * CC) + q * CC + hh * HD + dg) =
            make_float4(o4.x * inv, o4.y * inv, o4.z * inv, o4.w * inv);
    }
}

// ---------------------------------------------------------------
// Output projection: out[b][co][v] = proj_b[co] + sum_c proj_w[co][c]*g_O[b][v][c]
// ---------------------------------------------------------------
__global__ __launch_bounds__(256)
void oproj_kernel(const float* __restrict__ proj_w,
                  const float* __restrict__ proj_b,
                  float* __restrict__ out) {
    const int b = blockIdx.x;
    __shared__ float os[VQ * CC];
    const int tid = threadIdx.x;            // tid == co
    for (int i = tid; i < VQ * CC; i += 256) os[i] = g_O[b * (VQ * CC) + i];
    __syncthreads();

    float acc[VQ];
    const float bias = proj_b[tid];
#pragma unroll
    for (int v = 0; v < VQ; v++) acc[v] = bias;
    const float* wrow = proj_w + tid * CC;
    for (int c = 0; c < CC; c++) {
        float w = wrow[c];
#pragma unroll
        for (int v = 0; v < VQ; v++) acc[v] += w * os[v * CC + c];
    }
#pragma unroll
    for (int v = 0; v < VQ; v++)
        out[b * (CC * VQ) + tid * VQ + v] = acc[v];
}

// ---------------------------------------------------------------
extern "C" void kernel_launch(void* const* d_in, const int* in_sizes, int n_in,
                              void* d_out, int out_size) {
    (void)in_sizes; (void)n_in; (void)out_size;
    const float* x_cls   = (const float*)d_in[0];
    const float* x_patch = (const float*)d_in[1];
    const float* q_w     = (const float*)d_in[2];
    const float* k_w     = (const float*)d_in[3];
    const float* v_w     = (const float*)d_in[4];
    const float* temp    = (const float*)d_in[5];
    const float* proj_w  = (const float*)d_in[6];
    const float* proj_b  = (const float*)d_in[7];
    float* out = (float*)d_out;

    qproj_kernel<<<BB, 256>>>(x_cls, q_w, temp);

    dim3 gg(NTOK / 64, CC / 128, BB);   // (25, 2, 64)
    proj_gemm_kernel<<<gg, 128>>>(x_patch, k_w, 0);
    proj_gemm_kernel<<<gg, 128>>>(x_patch, v_w, 1);

    attn_kernel<<<BB * HH, 256>>>();

    oproj_kernel<<<BB, 256>>>(proj_w, proj_b, out);
}